// round 1
// baseline (speedup 1.0000x reference)
#include <cuda_runtime.h>
#include <math.h>

// Problem constants
#define BQ 2
#define CQ 128
#define TQ 32
#define NQ 512
#define PQ (TQ * NQ)      // 16384 points per batch
#define KQ 16
#define HIDQ 512
#define OUTC 132
#define THREEN 1536

// ---------------------------------------------------------------------------
// Device scratch (static — no allocations allowed)
// ---------------------------------------------------------------------------
__device__ float g_xpm[BQ * PQ * CQ];      // x transposed to (b, p, c)
__device__ float g_qkv[BQ * PQ * 384];     // (b, p, [q(128) | kx(128) | vx(128)])
__device__ int   g_idx[BQ * PQ * KQ];      // neighbor composite index t_eff*N + n'
__device__ float g_h[BQ * PQ * CQ];        // post-attention, post-BN h (point-major)
__device__ float g_hid[BQ * PQ * HIDQ];    // W1 output (point-major)

// ---------------------------------------------------------------------------
// K0: transpose x (B,C,P) -> g_xpm (B,P,C)
// ---------------------------------------------------------------------------
__global__ void k_transpose(const float* __restrict__ x)
{
    __shared__ float tile[32][33];
    int b = blockIdx.z;
    int p0 = blockIdx.x * 32;
    int c0 = blockIdx.y * 32;
    const float* xb = x + (size_t)b * CQ * PQ;
    int tx = threadIdx.x, ty = threadIdx.y;
#pragma unroll
    for (int i = 0; i < 32; i += 8)
        tile[ty + i][tx] = xb[(size_t)(c0 + ty + i) * PQ + p0 + tx];
    __syncthreads();
    float* op = g_xpm + (size_t)b * PQ * CQ;
#pragma unroll
    for (int i = 0; i < 32; i += 8)
        op[(size_t)(p0 + ty + i) * CQ + c0 + tx] = tile[tx][ty + i];
}

// ---------------------------------------------------------------------------
// K1: top-K neighbor selection.
// For each (b,t,n): distances from point n to 1536 candidates (3 coord chans),
// select K=16 smallest with tie-break on lower candidate index m (matches
// jax.lax.top_k on -d2). Candidates m: j=m/N in {0,1,2}, n'=m%N,
// t_eff = clamp(t-1+j, 0, T-1).
// Grid: (T, B, 8); block 256 threads (8 warps); each warp does 8 points.
// ---------------------------------------------------------------------------
__global__ void __launch_bounds__(256) k_topk(const float* __restrict__ x)
{
    int t = blockIdx.x, b = blockIdx.y, z = blockIdx.z;
    __shared__ float sc[3][THREEN];
    const float* xb = x + (size_t)b * CQ * PQ;
    int tid = threadIdx.x;

    for (int i = tid; i < 3 * THREEN; i += 256) {
        int c = i / THREEN, m = i % THREEN;
        int j = m >> 9, nn = m & 511;
        int te = t - 1 + j;
        te = te < 0 ? 0 : (te > TQ - 1 ? TQ - 1 : te);
        sc[c][m] = xb[(size_t)c * PQ + te * NQ + nn];
    }
    __syncthreads();

    int lane = tid & 31, w = tid >> 5;
    for (int i = 0; i < 8; i++) {
        int n = z * 64 + w * 8 + i;
        float a0 = sc[0][512 + n], a1 = sc[1][512 + n], a2 = sc[2][512 + n];
        float d[48];
#pragma unroll
        for (int jj = 0; jj < 48; jj++) {
            int m = jj * 32 + lane;
            float dx = sc[0][m] - a0;
            float dy = sc[1][m] - a1;
            float dz = sc[2][m] - a2;
            d[jj] = dx * dx + dy * dy + dz * dz;
        }
        unsigned long long removed = 0ull;
        int* orow = g_idx + ((size_t)(b * TQ + t) * NQ + n) * KQ;
        for (int it = 0; it < KQ; it++) {
            float best = 3.4e38f;
            int bj = 0;
#pragma unroll
            for (int jj = 0; jj < 48; jj++) {
                bool alive = !(removed & (1ull << jj));
                if (alive && d[jj] < best) { best = d[jj]; bj = jj; }
            }
            int bm = bj * 32 + lane;
            // warp argmin, lexicographic (d, m)
#pragma unroll
            for (int off = 16; off; off >>= 1) {
                float od = __shfl_xor_sync(0xffffffffu, best, off);
                int   om = __shfl_xor_sync(0xffffffffu, bm, off);
                if (od < best || (od == best && om < bm)) { best = od; bm = om; }
            }
            if ((bm & 31) == lane) removed |= (1ull << (bm >> 5));
            if (lane == 0) {
                int jwin = bm >> 9, nwin = bm & 511;
                int te = t - 1 + jwin;
                te = te < 0 ? 0 : (te > TQ - 1 ? TQ - 1 : te);
                orow[it] = te * NQ + nwin;
            }
        }
    }
}

// ---------------------------------------------------------------------------
// Generic fp32 GEMM tile core: 128 points x 128 cout, K = CIN, 8x8 microtile.
// CM=true: input channel-major (A[(ci)*PQ + p]), A already offset to (b,p0).
// CM=false: input point-major (A[p*CIN + ci]), A already offset to p0 row.
// W row-major (co, ci), already offset to co0 row.
// ---------------------------------------------------------------------------
template<int CIN, bool CM>
__device__ __forceinline__ void sgemm_tile(const float* __restrict__ A,
                                           const float* __restrict__ W,
                                           float acc[8][8], int tid)
{
    __shared__ float As[8][132];
    __shared__ float Bs[8][132];
    int tx = tid & 15, ty = tid >> 4;

#pragma unroll 1
    for (int kc = 0; kc < CIN / 8; kc++) {
        if (CM) {
            int kk = tid >> 5;
            int pp = (tid & 31) * 4;
            float4 v = *(const float4*)(A + (size_t)(kc * 8 + kk) * PQ + pp);
            *(float4*)&As[kk][pp] = v;
        } else {
            int pp = tid >> 1;
            int kk = (tid & 1) * 4;
            float4 v = *(const float4*)(A + (size_t)pp * CIN + kc * 8 + kk);
            As[kk + 0][pp] = v.x; As[kk + 1][pp] = v.y;
            As[kk + 2][pp] = v.z; As[kk + 3][pp] = v.w;
        }
        {
            int co = tid >> 1;
            int kk = (tid & 1) * 4;
            float4 v = *(const float4*)(W + (size_t)co * CIN + kc * 8 + kk);
            Bs[kk + 0][co] = v.x; Bs[kk + 1][co] = v.y;
            Bs[kk + 2][co] = v.z; Bs[kk + 3][co] = v.w;
        }
        __syncthreads();
#pragma unroll
        for (int kk = 0; kk < 8; kk++) {
            float a[8], bb[8];
            *(float4*)(a)      = *(const float4*)&As[kk][ty * 8];
            *(float4*)(a + 4)  = *(const float4*)&As[kk][ty * 8 + 4];
            *(float4*)(bb)     = *(const float4*)&Bs[kk][tx * 8];
            *(float4*)(bb + 4) = *(const float4*)&Bs[kk][tx * 8 + 4];
#pragma unroll
            for (int i = 0; i < 8; i++)
#pragma unroll
                for (int j = 0; j < 8; j++)
                    acc[i][j] += a[i] * bb[j];
        }
        __syncthreads();
    }
}

// K2: fused QKV projection. grid (128, 3, B): y selects Wq/Wk/Wv.
// Output point-major row of 384 floats: [q | kx | vx].
__global__ void __launch_bounds__(256) k_gemm_qkv(const float* __restrict__ x,
                                                  const float* __restrict__ Wq,
                                                  const float* __restrict__ Wk,
                                                  const float* __restrict__ Wv)
{
    int b = blockIdx.z;
    int p0 = blockIdx.x * 128;
    int cq = blockIdx.y;
    const float* W = (cq == 0) ? Wq : ((cq == 1) ? Wk : Wv);
    float acc[8][8] = {};
    sgemm_tile<128, true>(x + (size_t)b * CQ * PQ + p0, W, acc, threadIdx.x);

    int tx = threadIdx.x & 15, ty = threadIdx.x >> 4;
    float* out = g_qkv + ((size_t)(b * PQ + p0 + ty * 8)) * 384 + cq * 128 + tx * 8;
#pragma unroll
    for (int i = 0; i < 8; i++) {
        *(float4*)(out + (size_t)i * 384)     = make_float4(acc[i][0], acc[i][1], acc[i][2], acc[i][3]);
        *(float4*)(out + (size_t)i * 384 + 4) = make_float4(acc[i][4], acc[i][5], acc[i][6], acc[i][7]);
    }
}

// ---------------------------------------------------------------------------
// K3: attention + residual + BN. One warp handles one point at a time;
// lane l owns channels 4l..4l+3 (all within head l/8, since head = c/32).
// Grid: 512 blocks x 256 threads; 8 warps x 8 points = 64 points/block.
// ---------------------------------------------------------------------------
__global__ void __launch_bounds__(256) k_attn(const float* __restrict__ gamma,
                                              const float* __restrict__ beta,
                                              const float* __restrict__ mean,
                                              const float* __restrict__ var)
{
    __shared__ float s_scale[CQ], s_shift[CQ];
    int tid = threadIdx.x;
    if (tid < CQ) {
        float sc = gamma[tid] * rsqrtf(var[tid] + 1e-5f);
        s_scale[tid] = sc;
        s_shift[tid] = beta[tid] - mean[tid] * sc;
    }
    __syncthreads();

    int lane = tid & 31, w = tid >> 5;
    const float rs = 0.17677669529663687f; // 1/sqrt(32)

    for (int i = 0; i < 8; i++) {
        int g = blockIdx.x * 64 + w * 8 + i;   // global point index
        int b = g >> 14;
        int bbase = b << 14;

        const float4* qk = (const float4*)(g_qkv + (size_t)g * 384);
        float4 qv = qk[lane];
        float4 ks = qk[32 + lane];
        float4 vs = qk[64 + lane];

        const int* irow = g_idx + (size_t)g * KQ;
        int myidx = irow[lane & 15];

        float dself;
        {
            float p = qv.x * ks.x + qv.y * ks.y + qv.z * ks.z + qv.w * ks.w;
            p += __shfl_xor_sync(0xffffffffu, p, 1);
            p += __shfl_xor_sync(0xffffffffu, p, 2);
            p += __shfl_xor_sync(0xffffffffu, p, 4);
            dself = p;
        }

        float e[16];
#pragma unroll
        for (int k = 0; k < 16; k++) {
            int nb = __shfl_sync(0xffffffffu, myidx, k);
            const float4* kp = (const float4*)(g_qkv + (size_t)(bbase + nb) * 384 + 128);
            float4 kn = kp[lane];
            float p = qv.x * kn.x + qv.y * kn.y + qv.z * kn.z + qv.w * kn.w;
            p += __shfl_xor_sync(0xffffffffu, p, 1);
            p += __shfl_xor_sync(0xffffffffu, p, 2);
            p += __shfl_xor_sync(0xffffffffu, p, 4);
            e[k] = (dself - p) * rs;
        }

        float mx = e[0];
#pragma unroll
        for (int k = 1; k < 16; k++) mx = fmaxf(mx, e[k]);
        float s = 0.f;
#pragma unroll
        for (int k = 0; k < 16; k++) { e[k] = expf(e[k] - mx); s += e[k]; }
        float inv = 1.0f / s;

        float4 acc = vs;  // sum(attn) == 1 -> vx_self term
#pragma unroll
        for (int k = 0; k < 16; k++) {
            int nb = __shfl_sync(0xffffffffu, myidx, k);
            const float4* vp = (const float4*)(g_qkv + (size_t)(bbase + nb) * 384 + 256);
            float4 vn = vp[lane];
            float a = e[k] * inv;
            acc.x -= a * vn.x; acc.y -= a * vn.y;
            acc.z -= a * vn.z; acc.w -= a * vn.w;
        }

        const float4* xp = (const float4*)(g_xpm + (size_t)g * CQ);
        float4 xv = xp[lane];
        int c = lane * 4;
        float4 hv;
        hv.x = (xv.x + acc.x) * s_scale[c + 0] + s_shift[c + 0];
        hv.y = (xv.y + acc.y) * s_scale[c + 1] + s_shift[c + 1];
        hv.z = (xv.z + acc.z) * s_scale[c + 2] + s_shift[c + 2];
        hv.w = (xv.w + acc.w) * s_scale[c + 3] + s_shift[c + 3];
        ((float4*)(g_h + (size_t)g * CQ))[lane] = hv;
    }
}

// K4: hid = leaky_relu(W1 @ h). grid (128, 4, B). h,hid point-major.
__global__ void __launch_bounds__(256) k_gemm_w1(const float* __restrict__ W1)
{
    int p0g = blockIdx.z * PQ + blockIdx.x * 128;
    int co0 = blockIdx.y * 128;
    float acc[8][8] = {};
    sgemm_tile<128, false>(g_h + (size_t)p0g * CQ, W1 + (size_t)co0 * CQ, acc, threadIdx.x);

    int tx = threadIdx.x & 15, ty = threadIdx.x >> 4;
#pragma unroll
    for (int i = 0; i < 8; i++) {
#pragma unroll
        for (int j = 0; j < 8; j++) {
            float v = acc[i][j];
            acc[i][j] = v > 0.f ? v : 0.2f * v;
        }
        float* out = g_hid + (size_t)(p0g + ty * 8 + i) * HIDQ + co0 + tx * 8;
        *(float4*)(out)     = make_float4(acc[i][0], acc[i][1], acc[i][2], acc[i][3]);
        *(float4*)(out + 4) = make_float4(acc[i][4], acc[i][5], acc[i][6], acc[i][7]);
    }
}

// K5: y = W2 @ hid, written channel-major into d_out at channel offset 4.
// grid (128, 1, B).
__global__ void __launch_bounds__(256) k_gemm_w2(const float* __restrict__ W2,
                                                 float* __restrict__ out)
{
    int b = blockIdx.z;
    int p0 = blockIdx.x * 128;
    float acc[8][8] = {};
    sgemm_tile<512, false>(g_hid + (size_t)(b * PQ + p0) * HIDQ, W2, acc, threadIdx.x);

    int tx = threadIdx.x & 15, ty = threadIdx.x >> 4;
    float* ob = out + (size_t)b * OUTC * PQ + (size_t)4 * PQ;
#pragma unroll
    for (int j = 0; j < 8; j++) {
        int co = tx * 8 + j;
        float* dst = ob + (size_t)co * PQ + p0 + ty * 8;
        *(float4*)(dst)     = make_float4(acc[0][j], acc[1][j], acc[2][j], acc[3][j]);
        *(float4*)(dst + 4) = make_float4(acc[4][j], acc[5][j], acc[6][j], acc[7][j]);
    }
}

// ---------------------------------------------------------------------------
extern "C" void kernel_launch(void* const* d_in, const int* in_sizes, int n_in,
                              void* d_out, int out_size)
{
    const float* x     = (const float*)d_in[0];
    const float* Wq    = (const float*)d_in[1];
    const float* Wk    = (const float*)d_in[2];
    const float* Wv    = (const float*)d_in[3];
    const float* W1    = (const float*)d_in[4];
    const float* W2    = (const float*)d_in[5];
    const float* gamma = (const float*)d_in[6];
    const float* beta  = (const float*)d_in[7];
    const float* mean  = (const float*)d_in[8];
    const float* var   = (const float*)d_in[9];
    float* out = (float*)d_out;

    k_transpose<<<dim3(PQ / 32, CQ / 32, BQ), dim3(32, 8)>>>(x);
    k_topk<<<dim3(TQ, BQ, 8), 256>>>(x);
    k_gemm_qkv<<<dim3(PQ / 128, 3, BQ), 256>>>(x, Wq, Wk, Wv);
    k_attn<<<dim3((BQ * PQ) / 64, 1, 1), 256>>>(gamma, beta, mean, var);
    k_gemm_w1<<<dim3(PQ / 128, HIDQ / 128, BQ), 256>>>(W1);
    k_gemm_w2<<<dim3(PQ / 128, 1, BQ), 256>>>(W2, out);

    // out channels 0..3 = x channels 0..3 (contiguous blocks, D2D async copies)
    for (int b = 0; b < BQ; b++) {
        cudaMemcpyAsync(out + (size_t)b * OUTC * PQ,
                        x + (size_t)b * CQ * PQ,
                        (size_t)4 * PQ * sizeof(float),
                        cudaMemcpyDeviceToDevice);
    }
}

// round 2
// speedup vs baseline: 1.4918x; 1.4918x over previous
#include <cuda_runtime.h>
#include <math.h>
#include <stdint.h>

// Problem constants
#define BQ 2
#define CQ 128
#define TQ 32
#define NQ 512
#define PQ (TQ * NQ)      // 16384 points per batch
#define KQ 16
#define HIDQ 512
#define OUTC 132
#define THREEN 1536
#define KT 32             // GEMM K-tile

// ---------------------------------------------------------------------------
// Device scratch (static — no allocations allowed)
// ---------------------------------------------------------------------------
__device__ float g_xpm[BQ * PQ * CQ];      // x transposed to (b, p, c)
__device__ float g_qkv[BQ * PQ * 384];     // (b, p, [q(128) | kx(128) | vx(128)])
__device__ int   g_idx[BQ * PQ * KQ];      // neighbor composite index t_eff*N + n'
__device__ float g_h[BQ * PQ * CQ];        // post-attention, post-BN h (point-major)
__device__ float g_hid[BQ * PQ * HIDQ];    // W1 output (point-major)

// ---------------------------------------------------------------------------
// tf32 helpers
// ---------------------------------------------------------------------------
__device__ __forceinline__ uint32_t f2tf(float f)
{
    uint32_t r;
    asm("cvt.rna.tf32.f32 %0, %1;" : "=r"(r) : "f"(f));
    return r;
}

__device__ __forceinline__ void mma_tf32(float c[4],
                                         uint32_t a0, uint32_t a1, uint32_t a2, uint32_t a3,
                                         uint32_t b0, uint32_t b1)
{
    asm volatile(
        "mma.sync.aligned.m16n8k8.row.col.f32.tf32.tf32.f32 "
        "{%0,%1,%2,%3},{%4,%5,%6,%7},{%8,%9},{%0,%1,%2,%3};"
        : "+f"(c[0]), "+f"(c[1]), "+f"(c[2]), "+f"(c[3])
        : "r"(a0), "r"(a1), "r"(a2), "r"(a3), "r"(b0), "r"(b1));
}

// ---------------------------------------------------------------------------
// K0: transpose x (B,C,P) -> g_xpm (B,P,C)
// ---------------------------------------------------------------------------
__global__ void k_transpose(const float* __restrict__ x)
{
    __shared__ float tile[32][33];
    int b = blockIdx.z;
    int p0 = blockIdx.x * 32;
    int c0 = blockIdx.y * 32;
    const float* xb = x + (size_t)b * CQ * PQ;
    int tx = threadIdx.x, ty = threadIdx.y;
#pragma unroll
    for (int i = 0; i < 32; i += 8)
        tile[ty + i][tx] = xb[(size_t)(c0 + ty + i) * PQ + p0 + tx];
    __syncthreads();
    float* op = g_xpm + (size_t)b * PQ * CQ;
#pragma unroll
    for (int i = 0; i < 32; i += 8)
        op[(size_t)(p0 + ty + i) * CQ + c0 + tx] = tile[tx][ty + i];
}

// ---------------------------------------------------------------------------
// K1: top-K neighbor selection (unchanged from round 1 — correct & cheap).
// ---------------------------------------------------------------------------
__global__ void __launch_bounds__(256) k_topk(const float* __restrict__ x)
{
    int t = blockIdx.x, b = blockIdx.y, z = blockIdx.z;
    __shared__ float sc[3][THREEN];
    const float* xb = x + (size_t)b * CQ * PQ;
    int tid = threadIdx.x;

    for (int i = tid; i < 3 * THREEN; i += 256) {
        int c = i / THREEN, m = i % THREEN;
        int j = m >> 9, nn = m & 511;
        int te = t - 1 + j;
        te = te < 0 ? 0 : (te > TQ - 1 ? TQ - 1 : te);
        sc[c][m] = xb[(size_t)c * PQ + te * NQ + nn];
    }
    __syncthreads();

    int lane = tid & 31, w = tid >> 5;
    for (int i = 0; i < 8; i++) {
        int n = z * 64 + w * 8 + i;
        float a0 = sc[0][512 + n], a1 = sc[1][512 + n], a2 = sc[2][512 + n];
        float d[48];
#pragma unroll
        for (int jj = 0; jj < 48; jj++) {
            int m = jj * 32 + lane;
            float dx = sc[0][m] - a0;
            float dy = sc[1][m] - a1;
            float dz = sc[2][m] - a2;
            d[jj] = dx * dx + dy * dy + dz * dz;
        }
        unsigned long long removed = 0ull;
        int* orow = g_idx + ((size_t)(b * TQ + t) * NQ + n) * KQ;
        for (int it = 0; it < KQ; it++) {
            float best = 3.4e38f;
            int bj = 0;
#pragma unroll
            for (int jj = 0; jj < 48; jj++) {
                bool alive = !(removed & (1ull << jj));
                if (alive && d[jj] < best) { best = d[jj]; bj = jj; }
            }
            int bm = bj * 32 + lane;
#pragma unroll
            for (int off = 16; off; off >>= 1) {
                float od = __shfl_xor_sync(0xffffffffu, best, off);
                int   om = __shfl_xor_sync(0xffffffffu, bm, off);
                if (od < best || (od == best && om < bm)) { best = od; bm = om; }
            }
            if ((bm & 31) == lane) removed |= (1ull << (bm >> 5));
            if (lane == 0) {
                int jwin = bm >> 9, nwin = bm & 511;
                int te = t - 1 + jwin;
                te = te < 0 ? 0 : (te > TQ - 1 ? TQ - 1 : te);
                orow[it] = te * NQ + nwin;
            }
        }
    }
}

// ---------------------------------------------------------------------------
// tf32 MMA GEMM core: block tile 128 (M=points) x 128 (N=couts), K-step 32.
// 8 warps: wm = wid&1 (M 64), wn = wid>>2... wn = wid>>1 (N 32).
// Warp tile 64x32 -> 4 M-frags x 4 N-frags of m16n8k8.
// CM=true : A channel-major (A[k*PQ + m]), smem As[k][m] pad 136.
// CM=false: A point-major  (A[m*CIN + k]), smem As[m][k] pad 36.
// W row-major (n, k) -> Bs[n][k] pad 36. All frag loads bank-conflict-free.
// ---------------------------------------------------------------------------
template<int CIN, bool CM>
__device__ __forceinline__ void gemm_tile_tf32(const float* __restrict__ A,
                                               const float* __restrict__ W,
                                               float acc[4][4][4], int tid)
{
    __shared__ uint32_t As[CM ? (KT * 136) : (128 * 36)];
    __shared__ uint32_t Bs[128 * 36];

    const int lane = tid & 31;
    const int wid = tid >> 5;
    const int gid = lane >> 2;     // 0..7
    const int tig = lane & 3;      // 0..3
    const int mbase = (wid & 1) * 64;
    const int nbase = (wid >> 1) * 32;

#pragma unroll 1
    for (int kc = 0; kc < CIN / KT; kc++) {
        if (CM) {
            // 32 rows(k) x 128 cols(m): 1024 float4 loads
#pragma unroll
            for (int it = 0; it < 4; it++) {
                int idx = tid + it * 256;
                int r = idx >> 5, c4 = (idx & 31) * 4;
                float4 v = *(const float4*)(A + (size_t)(kc * KT + r) * PQ + c4);
                uint32_t* d = &As[r * 136 + c4];
                d[0] = f2tf(v.x); d[1] = f2tf(v.y); d[2] = f2tf(v.z); d[3] = f2tf(v.w);
            }
        } else {
#pragma unroll
            for (int it = 0; it < 4; it++) {
                int idx = tid + it * 256;
                int m = idx >> 3, k4 = (idx & 7) * 4;
                float4 v = *(const float4*)(A + (size_t)m * CIN + kc * KT + k4);
                uint32_t* d = &As[m * 36 + k4];
                d[0] = f2tf(v.x); d[1] = f2tf(v.y); d[2] = f2tf(v.z); d[3] = f2tf(v.w);
            }
        }
        {
#pragma unroll
            for (int it = 0; it < 4; it++) {
                int idx = tid + it * 256;
                int n = idx >> 3, k4 = (idx & 7) * 4;
                float4 v = *(const float4*)(W + (size_t)n * CIN + kc * KT + k4);
                uint32_t* d = &Bs[n * 36 + k4];
                d[0] = f2tf(v.x); d[1] = f2tf(v.y); d[2] = f2tf(v.z); d[3] = f2tf(v.w);
            }
        }
        __syncthreads();

#pragma unroll
        for (int ks = 0; ks < 4; ks++) {
            const int k0 = ks * 8;
            uint32_t af[4][4], bf[4][2];
#pragma unroll
            for (int mt = 0; mt < 4; mt++) {
                int m = mbase + mt * 16 + gid;
                if (CM) {
                    af[mt][0] = As[(k0 + tig) * 136 + m];
                    af[mt][1] = As[(k0 + tig) * 136 + m + 8];
                    af[mt][2] = As[(k0 + 4 + tig) * 136 + m];
                    af[mt][3] = As[(k0 + 4 + tig) * 136 + m + 8];
                } else {
                    af[mt][0] = As[m * 36 + k0 + tig];
                    af[mt][1] = As[(m + 8) * 36 + k0 + tig];
                    af[mt][2] = As[m * 36 + k0 + 4 + tig];
                    af[mt][3] = As[(m + 8) * 36 + k0 + 4 + tig];
                }
            }
#pragma unroll
            for (int nt = 0; nt < 4; nt++) {
                int n = nbase + nt * 8 + gid;
                bf[nt][0] = Bs[n * 36 + k0 + tig];
                bf[nt][1] = Bs[n * 36 + k0 + 4 + tig];
            }
#pragma unroll
            for (int mt = 0; mt < 4; mt++)
#pragma unroll
                for (int nt = 0; nt < 4; nt++)
                    mma_tf32(acc[mt][nt], af[mt][0], af[mt][1], af[mt][2], af[mt][3],
                             bf[nt][0], bf[nt][1]);
        }
        __syncthreads();
    }
}

// K2: fused QKV projection. grid (128, 3, B): y selects Wq/Wk/Wv.
__global__ void __launch_bounds__(256, 2) k_gemm_qkv(const float* __restrict__ x,
                                                     const float* __restrict__ Wq,
                                                     const float* __restrict__ Wk,
                                                     const float* __restrict__ Wv)
{
    int b = blockIdx.z;
    int p0 = blockIdx.x * 128;
    int cq = blockIdx.y;
    const float* W = (cq == 0) ? Wq : ((cq == 1) ? Wk : Wv);

    float acc[4][4][4] = {};
    gemm_tile_tf32<CQ, true>(x + (size_t)b * CQ * PQ + p0, W, acc, threadIdx.x);

    const int lane = threadIdx.x & 31, wid = threadIdx.x >> 5;
    const int gid = lane >> 2, tig = lane & 3;
    float* base = g_qkv + (size_t)(b * PQ + p0 + (wid & 1) * 64) * 384 + cq * 128 + (wid >> 1) * 32;
#pragma unroll
    for (int mt = 0; mt < 4; mt++) {
        int r = mt * 16 + gid;
#pragma unroll
        for (int nt = 0; nt < 4; nt++) {
            int c = nt * 8 + tig * 2;
            *(float2*)(base + (size_t)r * 384 + c)       = make_float2(acc[mt][nt][0], acc[mt][nt][1]);
            *(float2*)(base + (size_t)(r + 8) * 384 + c) = make_float2(acc[mt][nt][2], acc[mt][nt][3]);
        }
    }
}

// ---------------------------------------------------------------------------
// K3: attention + residual + BN (unchanged).
// ---------------------------------------------------------------------------
__global__ void __launch_bounds__(256) k_attn(const float* __restrict__ gamma,
                                              const float* __restrict__ beta,
                                              const float* __restrict__ mean,
                                              const float* __restrict__ var)
{
    __shared__ float s_scale[CQ], s_shift[CQ];
    int tid = threadIdx.x;
    if (tid < CQ) {
        float sc = gamma[tid] * rsqrtf(var[tid] + 1e-5f);
        s_scale[tid] = sc;
        s_shift[tid] = beta[tid] - mean[tid] * sc;
    }
    __syncthreads();

    int lane = tid & 31, w = tid >> 5;
    const float rs = 0.17677669529663687f; // 1/sqrt(32)

    for (int i = 0; i < 8; i++) {
        int g = blockIdx.x * 64 + w * 8 + i;
        int b = g >> 14;
        int bbase = b << 14;

        const float4* qk = (const float4*)(g_qkv + (size_t)g * 384);
        float4 qv = qk[lane];
        float4 ks = qk[32 + lane];
        float4 vs = qk[64 + lane];

        const int* irow = g_idx + (size_t)g * KQ;
        int myidx = irow[lane & 15];

        float dself;
        {
            float p = qv.x * ks.x + qv.y * ks.y + qv.z * ks.z + qv.w * ks.w;
            p += __shfl_xor_sync(0xffffffffu, p, 1);
            p += __shfl_xor_sync(0xffffffffu, p, 2);
            p += __shfl_xor_sync(0xffffffffu, p, 4);
            dself = p;
        }

        float e[16];
#pragma unroll
        for (int k = 0; k < 16; k++) {
            int nb = __shfl_sync(0xffffffffu, myidx, k);
            const float4* kp = (const float4*)(g_qkv + (size_t)(bbase + nb) * 384 + 128);
            float4 kn = kp[lane];
            float p = qv.x * kn.x + qv.y * kn.y + qv.z * kn.z + qv.w * kn.w;
            p += __shfl_xor_sync(0xffffffffu, p, 1);
            p += __shfl_xor_sync(0xffffffffu, p, 2);
            p += __shfl_xor_sync(0xffffffffu, p, 4);
            e[k] = (dself - p) * rs;
        }

        float mx = e[0];
#pragma unroll
        for (int k = 1; k < 16; k++) mx = fmaxf(mx, e[k]);
        float s = 0.f;
#pragma unroll
        for (int k = 0; k < 16; k++) { e[k] = expf(e[k] - mx); s += e[k]; }
        float inv = 1.0f / s;

        float4 acc = vs;
#pragma unroll
        for (int k = 0; k < 16; k++) {
            int nb = __shfl_sync(0xffffffffu, myidx, k);
            const float4* vp = (const float4*)(g_qkv + (size_t)(bbase + nb) * 384 + 256);
            float4 vn = vp[lane];
            float a = e[k] * inv;
            acc.x -= a * vn.x; acc.y -= a * vn.y;
            acc.z -= a * vn.z; acc.w -= a * vn.w;
        }

        const float4* xp = (const float4*)(g_xpm + (size_t)g * CQ);
        float4 xv = xp[lane];
        int c = lane * 4;
        float4 hv;
        hv.x = (xv.x + acc.x) * s_scale[c + 0] + s_shift[c + 0];
        hv.y = (xv.y + acc.y) * s_scale[c + 1] + s_shift[c + 1];
        hv.z = (xv.z + acc.z) * s_scale[c + 2] + s_shift[c + 2];
        hv.w = (xv.w + acc.w) * s_scale[c + 3] + s_shift[c + 3];
        ((float4*)(g_h + (size_t)g * CQ))[lane] = hv;
    }
}

// K4: hid = leaky_relu(W1 @ h). grid (128, 4, B).
__global__ void __launch_bounds__(256, 2) k_gemm_w1(const float* __restrict__ W1)
{
    int p0g = blockIdx.z * PQ + blockIdx.x * 128;
    int co0 = blockIdx.y * 128;

    float acc[4][4][4] = {};
    gemm_tile_tf32<CQ, false>(g_h + (size_t)p0g * CQ, W1 + (size_t)co0 * CQ, acc, threadIdx.x);

    const int lane = threadIdx.x & 31, wid = threadIdx.x >> 5;
    const int gid = lane >> 2, tig = lane & 3;
    float* base = g_hid + (size_t)(p0g + (wid & 1) * 64) * HIDQ + co0 + (wid >> 1) * 32;
#pragma unroll
    for (int mt = 0; mt < 4; mt++) {
        int r = mt * 16 + gid;
#pragma unroll
        for (int nt = 0; nt < 4; nt++) {
            int c = nt * 8 + tig * 2;
            float v0 = acc[mt][nt][0], v1 = acc[mt][nt][1];
            float v2 = acc[mt][nt][2], v3 = acc[mt][nt][3];
            v0 = v0 > 0.f ? v0 : 0.2f * v0;
            v1 = v1 > 0.f ? v1 : 0.2f * v1;
            v2 = v2 > 0.f ? v2 : 0.2f * v2;
            v3 = v3 > 0.f ? v3 : 0.2f * v3;
            *(float2*)(base + (size_t)r * HIDQ + c)       = make_float2(v0, v1);
            *(float2*)(base + (size_t)(r + 8) * HIDQ + c) = make_float2(v2, v3);
        }
    }
}

// K5: y = W2 @ hid, channel-major into d_out at channel offset 4. grid (128, 1, B).
__global__ void __launch_bounds__(256, 2) k_gemm_w2(const float* __restrict__ W2,
                                                    float* __restrict__ out)
{
    int b = blockIdx.z;
    int p0 = blockIdx.x * 128;

    float acc[4][4][4] = {};
    gemm_tile_tf32<HIDQ, false>(g_hid + (size_t)(b * PQ + p0) * HIDQ, W2, acc, threadIdx.x);

    const int lane = threadIdx.x & 31, wid = threadIdx.x >> 5;
    const int gid = lane >> 2, tig = lane & 3;
    float* ob = out + (size_t)b * OUTC * PQ + (size_t)4 * PQ;
    int rbase = p0 + (wid & 1) * 64;
    int cbase = (wid >> 1) * 32;
#pragma unroll
    for (int mt = 0; mt < 4; mt++) {
        int r = rbase + mt * 16 + gid;
#pragma unroll
        for (int nt = 0; nt < 4; nt++) {
            int c = cbase + nt * 8 + tig * 2;
            ob[(size_t)c * PQ + r]           = acc[mt][nt][0];
            ob[(size_t)(c + 1) * PQ + r]     = acc[mt][nt][1];
            ob[(size_t)c * PQ + r + 8]       = acc[mt][nt][2];
            ob[(size_t)(c + 1) * PQ + r + 8] = acc[mt][nt][3];
        }
    }
}

// ---------------------------------------------------------------------------
extern "C" void kernel_launch(void* const* d_in, const int* in_sizes, int n_in,
                              void* d_out, int out_size)
{
    const float* x     = (const float*)d_in[0];
    const float* Wq    = (const float*)d_in[1];
    const float* Wk    = (const float*)d_in[2];
    const float* Wv    = (const float*)d_in[3];
    const float* W1    = (const float*)d_in[4];
    const float* W2    = (const float*)d_in[5];
    const float* gamma = (const float*)d_in[6];
    const float* beta  = (const float*)d_in[7];
    const float* mean  = (const float*)d_in[8];
    const float* var   = (const float*)d_in[9];
    float* out = (float*)d_out;

    k_transpose<<<dim3(PQ / 32, CQ / 32, BQ), dim3(32, 8)>>>(x);
    k_topk<<<dim3(TQ, BQ, 8), 256>>>(x);
    k_gemm_qkv<<<dim3(PQ / 128, 3, BQ), 256>>>(x, Wq, Wk, Wv);
    k_attn<<<dim3((BQ * PQ) / 64, 1, 1), 256>>>(gamma, beta, mean, var);
    k_gemm_w1<<<dim3(PQ / 128, HIDQ / 128, BQ), 256>>>(W1);
    k_gemm_w2<<<dim3(PQ / 128, 1, BQ), 256>>>(W2, out);

    for (int b = 0; b < BQ; b++) {
        cudaMemcpyAsync(out + (size_t)b * OUTC * PQ,
                        x + (size_t)b * CQ * PQ,
                        (size_t)4 * PQ * sizeof(float),
                        cudaMemcpyDeviceToDevice);
    }
}